// round 14
// baseline (speedup 1.0000x reference)
#include <cuda_runtime.h>
#include <cstdint>
#include <cstddef>

#define HDIM   2048
#define NEXP   8
#define IDIM   1024
#define ISDIM  4096
#define TTOK   4096
#define ROWCAP 9216   // 2*TTOK + NEXP*128 padding

// ---------------- scratch (__device__ globals; no allocation allowed) ----------------
__device__ float g_h1[(size_t)ROWCAP * IDIM];     // expert SwiGLU output
__device__ float g_dout[(size_t)ROWCAP * HDIM];   // expert down output
__device__ float g_sg[(size_t)TTOK * ISDIM];      // shared SwiGLU output
__device__ int   g_rowmap[ROWCAP];
__device__ float g_roww[ROWCAP];
__device__ int   g_slot[TTOK * 2];
__device__ int   g_tokidx[TTOK * 2];
__device__ float g_tokw[TTOK * 2];
__device__ float g_gate[TTOK];
__device__ int   g_cnt[NEXP];
__device__ int   g_cursor[NEXP];
__device__ int   g_poff[NEXP + 1];

// tf32-pre-rounded copies (lets GEMMs use cp.async with no CVT in the pipeline)
__device__ float g_xr  [(size_t)TTOK * HDIM];
__device__ float g_wgr [(size_t)NEXP * HDIM * IDIM];
__device__ float g_wur [(size_t)NEXP * HDIM * IDIM];
__device__ float g_wdr [(size_t)NEXP * IDIM * HDIM];
__device__ float g_wsgr[(size_t)HDIM * ISDIM];
__device__ float g_wsur[(size_t)HDIM * ISDIM];
__device__ float g_wsdr[(size_t)ISDIM * HDIM];

// ---------------- helpers ----------------
__device__ __forceinline__ float to_tf32f(float x){
    unsigned u; asm("cvt.rna.tf32.f32 %0, %1;" : "=r"(u) : "f"(x));
    return __uint_as_float(u);
}
__device__ __forceinline__ float siluf(float x){
    return x * (1.f / (1.f + __expf(-x)));
}
__device__ __forceinline__ void mma_tf32(float* d, const unsigned* a, const unsigned* b){
    asm volatile("mma.sync.aligned.m16n8k8.row.col.f32.tf32.tf32.f32 "
                 "{%0,%1,%2,%3}, {%4,%5,%6,%7}, {%8,%9}, {%0,%1,%2,%3};\n"
                 : "+f"(d[0]), "+f"(d[1]), "+f"(d[2]), "+f"(d[3])
                 : "r"(a[0]), "r"(a[1]), "r"(a[2]), "r"(a[3]),
                   "r"(b[0]), "r"(b[1]));
}
__device__ __forceinline__ void cp16(unsigned dst, const void* src, int szbytes){
    asm volatile("cp.async.cg.shared.global [%0], [%1], 16, %2;\n"
                 :: "r"(dst), "l"(src), "r"(szbytes));
}
__device__ __forceinline__ void cp_commit(){ asm volatile("cp.async.commit_group;\n" ::: "memory"); }
template<int N> __device__ __forceinline__ void cp_wait(){
    asm volatile("cp.async.wait_group %0;\n" :: "n"(N) : "memory");
}

// ---------------- small kernels ----------------
__global__ void init_kernel(){
    int i = blockIdx.x * 256 + threadIdx.x;
    if (i < ROWCAP) g_rowmap[i] = -1;
    if (i < NEXP){ g_cnt[i] = 0; g_cursor[i] = 0; }
}

// round x + all weights to tf32 once (blockIdx.y selects array; dst chosen DEVICE-side)
__global__ void preround_kernel(const float4* __restrict__ x,
                                const float4* __restrict__ wg,
                                const float4* __restrict__ wu,
                                const float4* __restrict__ wd,
                                const float4* __restrict__ wsg,
                                const float4* __restrict__ wsu,
                                const float4* __restrict__ wsd)
{
    const float4* src; float4* dst; size_t n4;
    switch (blockIdx.y){
        case 0: src = wg;  dst = (float4*)g_wgr;  n4 = (size_t)NEXP*HDIM*IDIM/4; break;
        case 1: src = wu;  dst = (float4*)g_wur;  n4 = (size_t)NEXP*HDIM*IDIM/4; break;
        case 2: src = wd;  dst = (float4*)g_wdr;  n4 = (size_t)NEXP*IDIM*HDIM/4; break;
        case 3: src = x;   dst = (float4*)g_xr;   n4 = (size_t)TTOK*HDIM/4;      break;
        case 4: src = wsg; dst = (float4*)g_wsgr; n4 = (size_t)HDIM*ISDIM/4;     break;
        case 5: src = wsu; dst = (float4*)g_wsur; n4 = (size_t)HDIM*ISDIM/4;     break;
        default:src = wsd; dst = (float4*)g_wsdr; n4 = (size_t)ISDIM*HDIM/4;     break;
    }
    for (size_t i = (size_t)blockIdx.x * blockDim.x + threadIdx.x; i < n4;
         i += (size_t)gridDim.x * blockDim.x){
        float4 v = src[i];
        v.x = to_tf32f(v.x); v.y = to_tf32f(v.y);
        v.z = to_tf32f(v.z); v.w = to_tf32f(v.w);
        dst[i] = v;
    }
}

__global__ void router_kernel(const float* __restrict__ x,
                              const float* __restrict__ Wr,
                              const float* __restrict__ Wsgate,
                              float* __restrict__ logits_out)
{
    __shared__ float sW[128 * 8];
    __shared__ float sG[128];
    const int tok = blockIdx.x * 64 + threadIdx.x;

    float acc[9];
    #pragma unroll
    for (int e = 0; e < 9; e++) acc[e] = 0.f;

    for (int h0 = 0; h0 < HDIM; h0 += 128){
        __syncthreads();
        for (int i = threadIdx.x; i < 1024; i += 64) sW[i] = Wr[h0 * NEXP + i];
        for (int i = threadIdx.x; i < 128;  i += 64) sG[i] = Wsgate[h0 + i];
        __syncthreads();

        const float4* xr = (const float4*)(x + (size_t)tok * HDIM + h0);
        for (int k4 = 0; k4 < 32; k4++){
            float4 xv = xr[k4];
            float xs[4] = {xv.x, xv.y, xv.z, xv.w};
            #pragma unroll
            for (int j = 0; j < 4; j++){
                const int kk = k4 * 4 + j;
                const float xj = xs[j];
                #pragma unroll
                for (int e = 0; e < 8; e++)
                    acc[e] = fmaf(xj, sW[kk * 8 + e], acc[e]);
                acc[8] = fmaf(xj, sG[kk], acc[8]);
            }
        }
    }

    float4* lo = (float4*)(logits_out + (size_t)tok * 8);
    lo[0] = make_float4(acc[0], acc[1], acc[2], acc[3]);
    lo[1] = make_float4(acc[4], acc[5], acc[6], acc[7]);

    float mx = acc[0];
    #pragma unroll
    for (int e = 1; e < 8; e++) mx = fmaxf(mx, acc[e]);
    float ex[8];
    #pragma unroll
    for (int e = 0; e < 8; e++) ex[e] = __expf(acc[e] - mx);

    int i0 = 0; float v0 = ex[0];
    #pragma unroll
    for (int e = 1; e < 8; e++) if (ex[e] > v0){ v0 = ex[e]; i0 = e; }
    int i1 = -1; float v1 = -1.f;
    #pragma unroll
    for (int e = 0; e < 8; e++) if (e != i0 && ex[e] > v1){ v1 = ex[e]; i1 = e; }

    const float ws = v0 + v1;
    g_tokidx[2 * tok]     = i0;
    g_tokidx[2 * tok + 1] = i1;
    g_tokw[2 * tok]       = v0 / ws;
    g_tokw[2 * tok + 1]   = v1 / ws;
    g_gate[tok] = 1.f / (1.f + __expf(-acc[8]));

    atomicAdd(&g_cnt[i0], 1);
    atomicAdd(&g_cnt[i1], 1);
}

__global__ void scan_kernel(){
    if (threadIdx.x == 0 && blockIdx.x == 0){
        int off = 0;
        for (int e = 0; e < NEXP; e++){
            g_poff[e] = off;
            off += (g_cnt[e] + 127) & ~127;
        }
        g_poff[NEXP] = off;
    }
}

__global__ void scatter_kernel(){
    const int t = blockIdx.x * 256 + threadIdx.x;
    if (t >= TTOK) return;
    #pragma unroll
    for (int k = 0; k < 2; k++){
        const int e   = g_tokidx[2 * t + k];
        const int pos = g_poff[e] + atomicAdd(&g_cursor[e], 1);
        g_rowmap[pos] = t;
        g_roww[pos]   = g_tokw[2 * t + k];
        g_slot[2 * t + k] = pos;
    }
}

__global__ void combine_kernel(float* __restrict__ out){
    const int i = blockIdx.x * 256 + threadIdx.x;
    const int t = i >> 9;
    const int c = i & 511;
    const int s0 = g_slot[2 * t];
    const int s1 = g_slot[2 * t + 1];
    float4 o = ((float4*)out)[i];
    float4 a = ((const float4*)g_dout)[(size_t)s0 * 512 + c];
    float4 b = ((const float4*)g_dout)[(size_t)s1 * 512 + c];
    o.x += a.x + b.x; o.y += a.y + b.y; o.z += a.z + b.z; o.w += a.w + b.w;
    ((float4*)out)[i] = o;
}

// ---------------- pipelined TF32 GEMM, big warp tiles ----------------
// 128 threads (4 warps, 2x2 warp grid).
//   DUAL   modes: BM=128, BN=64,  warp tile 64x32 (acc0+acc1 = 128 regs)
//   SINGLE modes: BM=128, BN=128, warp tile 64x64 (acc = 128 regs)
// Per k-step: 32 MMAs vs 32 LDS (was 16 vs 24) -> +50% math per shared access.
// 3-stage cp.async pipeline; ~107-110KB smem/CTA -> 2 CTAs/SM (8 warps).
enum { MODE_GU_SH = 0, MODE_GU_EX = 1, MODE_DN_SH = 2, MODE_DN_EX = 3 };

template<int MODE>
__global__ __launch_bounds__(128, 2)
void gemm_kernel(float* __restrict__ Cout, int K, int N, int grid_m, int grid_n)
{
    constexpr bool DUAL   = (MODE == MODE_GU_SH || MODE == MODE_GU_EX);
    constexpr bool EXPERT = (MODE == MODE_GU_EX || MODE == MODE_DN_EX);
    constexpr bool GATHER = (MODE == MODE_GU_EX);
    constexpr int  BN     = DUAL ? 64 : 128;
    constexpr int  BSTR   = BN + 8;                 // padded B row stride (floats)
    constexpr int  NF     = DUAL ? 4 : 8;           // 8-col fragments per warp (per B)
    constexpr int  STG    = DUAL ? 9216 : 8960;     // floats per stage
    constexpr int  STAGES = 3;

    extern __shared__ float smem[];

    // device-side operand selection (never pass __device__ symbols from host)
    const float* A;
    const float* B0;
    const float* B1 = nullptr;
    if (MODE == MODE_GU_SH){ A = g_xr; B0 = g_wsgr; B1 = g_wsur; }
    if (MODE == MODE_GU_EX){ A = g_xr; B0 = g_wgr;  B1 = g_wur;  }
    if (MODE == MODE_DN_SH){ A = g_sg; B0 = g_wsdr; }
    if (MODE == MODE_DN_EX){ A = g_h1; B0 = g_wdr;  }

    // rasterized block mapping (GROUP_M m-tiles per n-panel for L2 reuse)
    const int GROUPM = 8;
    int lin = blockIdx.x;
    int per = GROUPM * grid_n;
    int g   = lin / per;
    int rem = lin - g * per;
    int gm  = min(GROUPM, grid_m - g * GROUPM);
    const int m0 = (g * GROUPM + rem % gm) * 128;
    const int n0 = (rem / gm) * BN;

    if (EXPERT){
        if (m0 >= g_poff[NEXP]) return;
        int e = 0;
        while (m0 >= g_poff[e + 1]) e++;
        const size_t boff = (size_t)e * K * N;
        B0 += boff;
        if (DUAL) B1 += boff;
    }

    const int tid = threadIdx.x;

    // ---- A loader: 128 rows x 32 cols, 16 rows/pass x 8 passes ----
    const int lrow = tid >> 3;                      // 0..15
    const int lk4  = (tid & 7) * 4;                 // 0..28
    const char* aSrc[8];
    unsigned aMask = 0;
    #pragma unroll
    for (int p = 0; p < 8; p++){
        const int r = m0 + lrow + 16 * p;
        if (GATHER){
            const int tk = g_rowmap[r];
            if (tk >= 0) aMask |= (1u << p);
            aSrc[p] = (const char*)(A + ((tk < 0) ? (size_t)0 : (size_t)tk * K) + lk4);
        } else {
            aMask |= (1u << p);
            aSrc[p] = (const char*)(A + (size_t)r * K + lk4);
        }
    }

    // ---- B loader: 32 rows x BN cols ----
    constexpr int TPR = BN / 4;                     // threads per B row (16 or 32)
    constexpr int RPP = 128 / TPR;                  // rows per pass (8 or 4)
    constexpr int QB  = 32 / RPP;                   // passes (4 or 8)
    const int lkrow = tid / TPR;                    // 0..RPP-1
    const int ln4   = (tid % TPR) * 4;
    const char* bSrc0 = (const char*)(B0 + (size_t)lkrow * N + n0 + ln4);
    const char* bSrc1 = DUAL ? (const char*)(B1 + (size_t)lkrow * N + n0 + ln4) : nullptr;

    const unsigned base_u = (unsigned)__cvta_generic_to_shared(smem);
    const unsigned aDst0  = (unsigned)((lrow * 36 + lk4) * 4);
    const unsigned bDst0  = (unsigned)((4608 + lkrow * BSTR + ln4) * 4);

    auto issue = [&](int kt, int st){
        const size_t k0b = (size_t)kt * 32 * 4;
        const unsigned sb = base_u + (unsigned)(st * STG * 4);
        #pragma unroll
        for (int p = 0; p < 8; p++)
            cp16(sb + aDst0 + (unsigned)(p * 16 * 36 * 4), aSrc[p] + k0b,
                 (aMask >> p & 1) ? 16 : 0);
        #pragma unroll
        for (int q = 0; q < QB; q++){
            const size_t boffb = ((size_t)kt * 32 + RPP * q) * (size_t)N * 4;
            const unsigned d = bDst0 + (unsigned)(q * RPP * BSTR * 4);
            cp16(sb + d, bSrc0 + boffb, 16);
            if (DUAL) cp16(sb + d + 2304 * 4, bSrc1 + boffb, 16);
        }
    };

    // ---- warp / lane coords (2x2 warp grid) ----
    const int wid  = tid >> 5;
    const int wm   = (wid & 1) * 64;
    const int wn   = (wid >> 1) * (DUAL ? 32 : 64);
    const int lane = tid & 31;
    const int gid  = lane >> 2;
    const int tg   = lane & 3;

    float acc0[4][NF][4];
    float acc1[DUAL ? 4 : 1][NF][4];
    #pragma unroll
    for (int a = 0; a < 4; a++)
        #pragma unroll
        for (int b = 0; b < NF; b++)
            #pragma unroll
            for (int c = 0; c < 4; c++){
                acc0[a][b][c] = 0.f;
                if (DUAL) acc1[DUAL ? a : 0][b][c] = 0.f;
            }

    auto compute = [&](int st){
        const float* Asb = smem + st * STG;
        const float* B0b = Asb + 4608;
        const float* B1b = Asb + 4608 + 2304;
        #pragma unroll
        for (int ks = 0; ks < 4; ks++){
            const int k8 = ks * 8;
            unsigned af[4][4];
            #pragma unroll
            for (int mf = 0; mf < 4; mf++){
                const int mr = wm + mf * 16 + gid;
                af[mf][0] = __float_as_uint(Asb[(mr    ) * 36 + k8 + tg    ]);
                af[mf][1] = __float_as_uint(Asb[(mr + 8) * 36 + k8 + tg    ]);
                af[mf][2] = __float_as_uint(Asb[(mr    ) * 36 + k8 + 4 + tg]);
                af[mf][3] = __float_as_uint(Asb[(mr + 8) * 36 + k8 + 4 + tg]);
            }
            unsigned bf0[NF][2], bf1[NF][2];
            #pragma unroll
            for (int nf = 0; nf < NF; nf++){
                const int nc = wn + nf * 8 + gid;
                bf0[nf][0] = __float_as_uint(B0b[(k8 + tg    ) * BSTR + nc]);
                bf0[nf][1] = __float_as_uint(B0b[(k8 + 4 + tg) * BSTR + nc]);
                if (DUAL){
                    bf1[nf][0] = __float_as_uint(B1b[(k8 + tg    ) * BSTR + nc]);
                    bf1[nf][1] = __float_as_uint(B1b[(k8 + 4 + tg) * BSTR + nc]);
                }
            }
            #pragma unroll
            for (int mf = 0; mf < 4; mf++)
                #pragma unroll
                for (int nf = 0; nf < NF; nf++){
                    mma_tf32(acc0[mf][nf], af[mf], bf0[nf]);
                    if (DUAL) mma_tf32(acc1[DUAL ? mf : 0][nf], af[mf], bf1[nf]);
                }
        }
    };

    const int KT = K >> 5;

    // pipeline prologue: STAGES-1 stages in flight
    #pragma unroll
    for (int s = 0; s < STAGES - 1; s++){
        if (s < KT) issue(s, s);
        cp_commit();
    }

    for (int kt = 0; kt < KT; kt++){
        cp_wait<STAGES - 2>();
        __syncthreads();
        const int nx = kt + STAGES - 1;
        if (nx < KT) issue(nx, nx % STAGES);
        cp_commit();                               // always commit: keeps group count aligned
        compute(kt % STAGES);
    }

    // epilogue
    #pragma unroll
    for (int mf = 0; mf < 4; mf++){
        #pragma unroll
        for (int nf = 0; nf < NF; nf++){
            const int r0 = m0 + wm + mf * 16 + gid;
            const int r1 = r0 + 8;
            const int c  = n0 + wn + nf * 8 + 2 * tg;
            const float* a0v = acc0[mf][nf];
            if (DUAL){
                const float* a1v = acc1[DUAL ? mf : 0][nf];
                float* Cb = (MODE == MODE_GU_SH) ? g_sg : g_h1;   // device-side
                float2 v0 = make_float2(to_tf32f(siluf(a0v[0]) * a1v[0]),
                                        to_tf32f(siluf(a0v[1]) * a1v[1]));
                float2 v1 = make_float2(to_tf32f(siluf(a0v[2]) * a1v[2]),
                                        to_tf32f(siluf(a0v[3]) * a1v[3]));
                *(float2*)&Cb[(size_t)r0 * N + c] = v0;
                *(float2*)&Cb[(size_t)r1 * N + c] = v1;
            } else if (MODE == MODE_DN_SH){
                const float s0 = g_gate[r0], s1 = g_gate[r1];
                float2 v0 = make_float2(a0v[0] * s0, a0v[1] * s0);
                float2 v1 = make_float2(a0v[2] * s1, a0v[3] * s1);
                *(float2*)&Cout[(size_t)r0 * N + c] = v0;
                *(float2*)&Cout[(size_t)r1 * N + c] = v1;
            } else { // MODE_DN_EX
                const float s0 = g_roww[r0], s1 = g_roww[r1];
                float2 v0 = make_float2(a0v[0] * s0, a0v[1] * s0);
                float2 v1 = make_float2(a0v[2] * s1, a0v[3] * s1);
                *(float2*)&g_dout[(size_t)r0 * N + c] = v0;
                *(float2*)&g_dout[(size_t)r1 * N + c] = v1;
            }
        }
    }
}

// ---------------- launch ----------------
extern "C" void kernel_launch(void* const* d_in, const int* in_sizes, int n_in,
                              void* d_out, int out_size)
{
    (void)in_sizes; (void)n_in; (void)out_size;

    const float* x      = (const float*)d_in[0];
    const float* Wr     = (const float*)d_in[1];
    const float* Wg     = (const float*)d_in[2];
    const float* Wu     = (const float*)d_in[3];
    const float* Wd     = (const float*)d_in[4];
    const float* Wsg    = (const float*)d_in[5];
    const float* Wsu    = (const float*)d_in[6];
    const float* Wsd    = (const float*)d_in[7];
    const float* Wsgate = (const float*)d_in[8];

    float* out    = (float*)d_out;
    float* logits = out + (size_t)TTOK * HDIM;

    const int SMEM_DUAL = 3 * 9216 * 4;   // 110592 B
    const int SMEM_SGL  = 3 * 8960 * 4;   // 107520 B
    cudaFuncSetAttribute(gemm_kernel<MODE_GU_SH>, cudaFuncAttributeMaxDynamicSharedMemorySize, SMEM_DUAL);
    cudaFuncSetAttribute(gemm_kernel<MODE_GU_EX>, cudaFuncAttributeMaxDynamicSharedMemorySize, SMEM_DUAL);
    cudaFuncSetAttribute(gemm_kernel<MODE_DN_SH>, cudaFuncAttributeMaxDynamicSharedMemorySize, SMEM_SGL);
    cudaFuncSetAttribute(gemm_kernel<MODE_DN_EX>, cudaFuncAttributeMaxDynamicSharedMemorySize, SMEM_SGL);

    // launch order chosen so the profiler's sample index lands on the big GEMM
    init_kernel<<<(ROWCAP + 255) / 256, 256>>>();                                   // 0
    preround_kernel<<<dim3(16384, 7), 256>>>((const float4*)x, (const float4*)Wg,   // 1
                                             (const float4*)Wu, (const float4*)Wd,
                                             (const float4*)Wsg, (const float4*)Wsu,
                                             (const float4*)Wsd);
    router_kernel<<<TTOK / 64, 64>>>(x, Wr, Wsgate, logits);                        // 2

    {   // 3: shared expert gate+up SwiGLU  (profiler target)
        int gm = TTOK / 128, gn = ISDIM / 64;
        gemm_kernel<MODE_GU_SH><<<gm * gn, 128, SMEM_DUAL>>>(nullptr, HDIM, ISDIM, gm, gn);
    }

    scan_kernel<<<1, 32>>>();                                                       // 4
    scatter_kernel<<<TTOK / 256, 256>>>();                                          // 5

    {   // shared expert down (sigmoid-gated) -> out
        int gm = TTOK / 128, gn = HDIM / 128;
        gemm_kernel<MODE_DN_SH><<<gm * gn, 128, SMEM_SGL>>>(out, ISDIM, HDIM, gm, gn);
    }
    {   // expert gate+up SwiGLU (gathered rows)
        int gm = ROWCAP / 128, gn = IDIM / 64;
        gemm_kernel<MODE_GU_EX><<<gm * gn, 128, SMEM_DUAL>>>(nullptr, HDIM, IDIM, gm, gn);
    }
    {   // expert down (routing weight folded) -> g_dout
        int gm = ROWCAP / 128, gn = HDIM / 128;
        gemm_kernel<MODE_DN_EX><<<gm * gn, 128, SMEM_SGL>>>(nullptr, IDIM, HDIM, gm, gn);
    }

    // out += dout[slot0] + dout[slot1]
    combine_kernel<<<(TTOK * HDIM / 4) / 256, 256>>>(out);
}

// round 15
// speedup vs baseline: 1.0013x; 1.0013x over previous
#include <cuda_runtime.h>
#include <cstdint>
#include <cstddef>

#define HDIM   2048
#define NEXP   8
#define IDIM   1024
#define ISDIM  4096
#define TTOK   4096
#define ROWCAP 9216   // 2*TTOK + NEXP*128 padding

// ---------------- scratch (__device__ globals; no allocation allowed) ----------------
__device__ float g_h1[(size_t)ROWCAP * IDIM];     // expert SwiGLU output
__device__ float g_dout[(size_t)ROWCAP * HDIM];   // expert down output
__device__ float g_sg[(size_t)TTOK * ISDIM];      // shared SwiGLU output
__device__ int   g_rowmap[ROWCAP];
__device__ float g_roww[ROWCAP];
__device__ int   g_slot[TTOK * 2];
__device__ int   g_tokidx[TTOK * 2];
__device__ float g_tokw[TTOK * 2];
__device__ float g_gate[TTOK];
__device__ int   g_cnt[NEXP];
__device__ int   g_cursor[NEXP];
__device__ int   g_poff[NEXP + 1];

// tf32-pre-rounded copies (lets GEMMs use cp.async with no CVT in the pipeline)
__device__ float g_xr  [(size_t)TTOK * HDIM];
__device__ float g_wgr [(size_t)NEXP * HDIM * IDIM];
__device__ float g_wur [(size_t)NEXP * HDIM * IDIM];
__device__ float g_wdr [(size_t)NEXP * IDIM * HDIM];
__device__ float g_wsgr[(size_t)HDIM * ISDIM];
__device__ float g_wsur[(size_t)HDIM * ISDIM];
__device__ float g_wsdr[(size_t)ISDIM * HDIM];

// ---------------- helpers ----------------
__device__ __forceinline__ float to_tf32f(float x){
    unsigned u; asm("cvt.rna.tf32.f32 %0, %1;" : "=r"(u) : "f"(x));
    return __uint_as_float(u);
}
__device__ __forceinline__ float siluf(float x){
    return x * (1.f / (1.f + __expf(-x)));
}
__device__ __forceinline__ void mma_tf32(float* d, const unsigned* a, const unsigned* b){
    asm volatile("mma.sync.aligned.m16n8k8.row.col.f32.tf32.tf32.f32 "
                 "{%0,%1,%2,%3}, {%4,%5,%6,%7}, {%8,%9}, {%0,%1,%2,%3};\n"
                 : "+f"(d[0]), "+f"(d[1]), "+f"(d[2]), "+f"(d[3])
                 : "r"(a[0]), "r"(a[1]), "r"(a[2]), "r"(a[3]),
                   "r"(b[0]), "r"(b[1]));
}
__device__ __forceinline__ void cp16(unsigned dst, const void* src, int szbytes){
    asm volatile("cp.async.cg.shared.global [%0], [%1], 16, %2;\n"
                 :: "r"(dst), "l"(src), "r"(szbytes));
}
__device__ __forceinline__ void cp_commit(){ asm volatile("cp.async.commit_group;\n" ::: "memory"); }
template<int N> __device__ __forceinline__ void cp_wait(){
    asm volatile("cp.async.wait_group %0;\n" :: "n"(N) : "memory");
}

// ---------------- small kernels ----------------
__global__ void init_kernel(){
    int i = blockIdx.x * 256 + threadIdx.x;
    if (i < ROWCAP) g_rowmap[i] = -1;
    if (i < NEXP){ g_cnt[i] = 0; g_cursor[i] = 0; }
}

// round x + all weights to tf32 once (blockIdx.y selects array; dst chosen DEVICE-side)
__global__ void preround_kernel(const float4* __restrict__ x,
                                const float4* __restrict__ wg,
                                const float4* __restrict__ wu,
                                const float4* __restrict__ wd,
                                const float4* __restrict__ wsg,
                                const float4* __restrict__ wsu,
                                const float4* __restrict__ wsd)
{
    const float4* src; float4* dst; size_t n4;
    switch (blockIdx.y){
        case 0: src = wg;  dst = (float4*)g_wgr;  n4 = (size_t)NEXP*HDIM*IDIM/4; break;
        case 1: src = wu;  dst = (float4*)g_wur;  n4 = (size_t)NEXP*HDIM*IDIM/4; break;
        case 2: src = wd;  dst = (float4*)g_wdr;  n4 = (size_t)NEXP*IDIM*HDIM/4; break;
        case 3: src = x;   dst = (float4*)g_xr;   n4 = (size_t)TTOK*HDIM/4;      break;
        case 4: src = wsg; dst = (float4*)g_wsgr; n4 = (size_t)HDIM*ISDIM/4;     break;
        case 5: src = wsu; dst = (float4*)g_wsur; n4 = (size_t)HDIM*ISDIM/4;     break;
        default:src = wsd; dst = (float4*)g_wsdr; n4 = (size_t)ISDIM*HDIM/4;     break;
    }
    for (size_t i = (size_t)blockIdx.x * blockDim.x + threadIdx.x; i < n4;
         i += (size_t)gridDim.x * blockDim.x){
        float4 v = src[i];
        v.x = to_tf32f(v.x); v.y = to_tf32f(v.y);
        v.z = to_tf32f(v.z); v.w = to_tf32f(v.w);
        dst[i] = v;
    }
}

__global__ void router_kernel(const float* __restrict__ x,
                              const float* __restrict__ Wr,
                              const float* __restrict__ Wsgate,
                              float* __restrict__ logits_out)
{
    __shared__ float sW[128 * 8];
    __shared__ float sG[128];
    const int tok = blockIdx.x * 64 + threadIdx.x;

    float acc[9];
    #pragma unroll
    for (int e = 0; e < 9; e++) acc[e] = 0.f;

    for (int h0 = 0; h0 < HDIM; h0 += 128){
        __syncthreads();
        for (int i = threadIdx.x; i < 1024; i += 64) sW[i] = Wr[h0 * NEXP + i];
        for (int i = threadIdx.x; i < 128;  i += 64) sG[i] = Wsgate[h0 + i];
        __syncthreads();

        const float4* xr = (const float4*)(x + (size_t)tok * HDIM + h0);
        for (int k4 = 0; k4 < 32; k4++){
            float4 xv = xr[k4];
            float xs[4] = {xv.x, xv.y, xv.z, xv.w};
            #pragma unroll
            for (int j = 0; j < 4; j++){
                const int kk = k4 * 4 + j;
                const float xj = xs[j];
                #pragma unroll
                for (int e = 0; e < 8; e++)
                    acc[e] = fmaf(xj, sW[kk * 8 + e], acc[e]);
                acc[8] = fmaf(xj, sG[kk], acc[8]);
            }
        }
    }

    float4* lo = (float4*)(logits_out + (size_t)tok * 8);
    lo[0] = make_float4(acc[0], acc[1], acc[2], acc[3]);
    lo[1] = make_float4(acc[4], acc[5], acc[6], acc[7]);

    float mx = acc[0];
    #pragma unroll
    for (int e = 1; e < 8; e++) mx = fmaxf(mx, acc[e]);
    float ex[8];
    #pragma unroll
    for (int e = 0; e < 8; e++) ex[e] = __expf(acc[e] - mx);

    int i0 = 0; float v0 = ex[0];
    #pragma unroll
    for (int e = 1; e < 8; e++) if (ex[e] > v0){ v0 = ex[e]; i0 = e; }
    int i1 = -1; float v1 = -1.f;
    #pragma unroll
    for (int e = 0; e < 8; e++) if (e != i0 && ex[e] > v1){ v1 = ex[e]; i1 = e; }

    const float ws = v0 + v1;
    g_tokidx[2 * tok]     = i0;
    g_tokidx[2 * tok + 1] = i1;
    g_tokw[2 * tok]       = v0 / ws;
    g_tokw[2 * tok + 1]   = v1 / ws;
    g_gate[tok] = 1.f / (1.f + __expf(-acc[8]));

    atomicAdd(&g_cnt[i0], 1);
    atomicAdd(&g_cnt[i1], 1);
}

__global__ void scan_kernel(){
    if (threadIdx.x == 0 && blockIdx.x == 0){
        int off = 0;
        for (int e = 0; e < NEXP; e++){
            g_poff[e] = off;
            off += (g_cnt[e] + 127) & ~127;
        }
        g_poff[NEXP] = off;
    }
}

__global__ void scatter_kernel(){
    const int t = blockIdx.x * 256 + threadIdx.x;
    if (t >= TTOK) return;
    #pragma unroll
    for (int k = 0; k < 2; k++){
        const int e   = g_tokidx[2 * t + k];
        const int pos = g_poff[e] + atomicAdd(&g_cursor[e], 1);
        g_rowmap[pos] = t;
        g_roww[pos]   = g_tokw[2 * t + k];
        g_slot[2 * t + k] = pos;
    }
}

__global__ void combine_kernel(float* __restrict__ out){
    const int i = blockIdx.x * 256 + threadIdx.x;
    const int t = i >> 9;
    const int c = i & 511;
    const int s0 = g_slot[2 * t];
    const int s1 = g_slot[2 * t + 1];
    float4 o = ((float4*)out)[i];
    float4 a = ((const float4*)g_dout)[(size_t)s0 * 512 + c];
    float4 b = ((const float4*)g_dout)[(size_t)s1 * 512 + c];
    o.x += a.x + b.x; o.y += a.y + b.y; o.z += a.z + b.z; o.w += a.w + b.w;
    ((float4*)out)[i] = o;
}

// ---------------- pipelined TF32 GEMM, big warp tiles ----------------
// 128 threads (4 warps, 2x2 warp grid).
//   DUAL   modes: BM=128, BN=64,  warp tile 64x32 (acc0+acc1 = 128 regs)
//   SINGLE modes: BM=128, BN=128, warp tile 64x64 (acc = 128 regs)
// Per k-step: 32 MMAs vs 32 LDS (was 16 vs 24) -> +50% math per shared access.
// 3-stage cp.async pipeline; ~107-110KB smem/CTA -> 2 CTAs/SM (8 warps).
enum { MODE_GU_SH = 0, MODE_GU_EX = 1, MODE_DN_SH = 2, MODE_DN_EX = 3 };

template<int MODE>
__global__ __launch_bounds__(128, 2)
void gemm_kernel(float* __restrict__ Cout, int K, int N, int grid_m, int grid_n)
{
    constexpr bool DUAL   = (MODE == MODE_GU_SH || MODE == MODE_GU_EX);
    constexpr bool EXPERT = (MODE == MODE_GU_EX || MODE == MODE_DN_EX);
    constexpr bool GATHER = (MODE == MODE_GU_EX);
    constexpr int  BN     = DUAL ? 64 : 128;
    constexpr int  BSTR   = BN + 8;                 // padded B row stride (floats)
    constexpr int  NF     = DUAL ? 4 : 8;           // 8-col fragments per warp (per B)
    constexpr int  STG    = DUAL ? 9216 : 8960;     // floats per stage
    constexpr int  STAGES = 3;

    extern __shared__ float smem[];

    // device-side operand selection (never pass __device__ symbols from host)
    const float* A;
    const float* B0;
    const float* B1 = nullptr;
    if (MODE == MODE_GU_SH){ A = g_xr; B0 = g_wsgr; B1 = g_wsur; }
    if (MODE == MODE_GU_EX){ A = g_xr; B0 = g_wgr;  B1 = g_wur;  }
    if (MODE == MODE_DN_SH){ A = g_sg; B0 = g_wsdr; }
    if (MODE == MODE_DN_EX){ A = g_h1; B0 = g_wdr;  }

    // rasterized block mapping (GROUP_M m-tiles per n-panel for L2 reuse)
    const int GROUPM = 8;
    int lin = blockIdx.x;
    int per = GROUPM * grid_n;
    int g   = lin / per;
    int rem = lin - g * per;
    int gm  = min(GROUPM, grid_m - g * GROUPM);
    const int m0 = (g * GROUPM + rem % gm) * 128;
    const int n0 = (rem / gm) * BN;

    if (EXPERT){
        if (m0 >= g_poff[NEXP]) return;
        int e = 0;
        while (m0 >= g_poff[e + 1]) e++;
        const size_t boff = (size_t)e * K * N;
        B0 += boff;
        if (DUAL) B1 += boff;
    }

    const int tid = threadIdx.x;

    // ---- A loader: 128 rows x 32 cols, 16 rows/pass x 8 passes ----
    const int lrow = tid >> 3;                      // 0..15
    const int lk4  = (tid & 7) * 4;                 // 0..28
    const char* aSrc[8];
    unsigned aMask = 0;
    #pragma unroll
    for (int p = 0; p < 8; p++){
        const int r = m0 + lrow + 16 * p;
        if (GATHER){
            const int tk = g_rowmap[r];
            if (tk >= 0) aMask |= (1u << p);
            aSrc[p] = (const char*)(A + ((tk < 0) ? (size_t)0 : (size_t)tk * K) + lk4);
        } else {
            aMask |= (1u << p);
            aSrc[p] = (const char*)(A + (size_t)r * K + lk4);
        }
    }

    // ---- B loader: 32 rows x BN cols ----
    constexpr int TPR = BN / 4;                     // threads per B row (16 or 32)
    constexpr int RPP = 128 / TPR;                  // rows per pass (8 or 4)
    constexpr int QB  = 32 / RPP;                   // passes (4 or 8)
    const int lkrow = tid / TPR;                    // 0..RPP-1
    const int ln4   = (tid % TPR) * 4;
    const char* bSrc0 = (const char*)(B0 + (size_t)lkrow * N + n0 + ln4);
    const char* bSrc1 = DUAL ? (const char*)(B1 + (size_t)lkrow * N + n0 + ln4) : nullptr;

    const unsigned base_u = (unsigned)__cvta_generic_to_shared(smem);
    const unsigned aDst0  = (unsigned)((lrow * 36 + lk4) * 4);
    const unsigned bDst0  = (unsigned)((4608 + lkrow * BSTR + ln4) * 4);

    auto issue = [&](int kt, int st){
        const size_t k0b = (size_t)kt * 32 * 4;
        const unsigned sb = base_u + (unsigned)(st * STG * 4);
        #pragma unroll
        for (int p = 0; p < 8; p++)
            cp16(sb + aDst0 + (unsigned)(p * 16 * 36 * 4), aSrc[p] + k0b,
                 (aMask >> p & 1) ? 16 : 0);
        #pragma unroll
        for (int q = 0; q < QB; q++){
            const size_t boffb = ((size_t)kt * 32 + RPP * q) * (size_t)N * 4;
            const unsigned d = bDst0 + (unsigned)(q * RPP * BSTR * 4);
            cp16(sb + d, bSrc0 + boffb, 16);
            if (DUAL) cp16(sb + d + 2304 * 4, bSrc1 + boffb, 16);
        }
    };

    // ---- warp / lane coords (2x2 warp grid) ----
    const int wid  = tid >> 5;
    const int wm   = (wid & 1) * 64;
    const int wn   = (wid >> 1) * (DUAL ? 32 : 64);
    const int lane = tid & 31;
    const int gid  = lane >> 2;
    const int tg   = lane & 3;

    float acc0[4][NF][4];
    float acc1[DUAL ? 4 : 1][NF][4];
    #pragma unroll
    for (int a = 0; a < 4; a++)
        #pragma unroll
        for (int b = 0; b < NF; b++)
            #pragma unroll
            for (int c = 0; c < 4; c++){
                acc0[a][b][c] = 0.f;
                if (DUAL) acc1[DUAL ? a : 0][b][c] = 0.f;
            }

    auto compute = [&](int st){
        const float* Asb = smem + st * STG;
        const float* B0b = Asb + 4608;
        const float* B1b = Asb + 4608 + 2304;
        #pragma unroll
        for (int ks = 0; ks < 4; ks++){
            const int k8 = ks * 8;
            unsigned af[4][4];
            #pragma unroll
            for (int mf = 0; mf < 4; mf++){
                const int mr = wm + mf * 16 + gid;
                af[mf][0] = __float_as_uint(Asb[(mr    ) * 36 + k8 + tg    ]);
                af[mf][1] = __float_as_uint(Asb[(mr + 8) * 36 + k8 + tg    ]);
                af[mf][2] = __float_as_uint(Asb[(mr    ) * 36 + k8 + 4 + tg]);
                af[mf][3] = __float_as_uint(Asb[(mr + 8) * 36 + k8 + 4 + tg]);
            }
            unsigned bf0[NF][2], bf1[NF][2];
            #pragma unroll
            for (int nf = 0; nf < NF; nf++){
                const int nc = wn + nf * 8 + gid;
                bf0[nf][0] = __float_as_uint(B0b[(k8 + tg    ) * BSTR + nc]);
                bf0[nf][1] = __float_as_uint(B0b[(k8 + 4 + tg) * BSTR + nc]);
                if (DUAL){
                    bf1[nf][0] = __float_as_uint(B1b[(k8 + tg    ) * BSTR + nc]);
                    bf1[nf][1] = __float_as_uint(B1b[(k8 + 4 + tg) * BSTR + nc]);
                }
            }
            #pragma unroll
            for (int mf = 0; mf < 4; mf++)
                #pragma unroll
                for (int nf = 0; nf < NF; nf++){
                    mma_tf32(acc0[mf][nf], af[mf], bf0[nf]);
                    if (DUAL) mma_tf32(acc1[DUAL ? mf : 0][nf], af[mf], bf1[nf]);
                }
        }
    };

    const int KT = K >> 5;

    // pipeline prologue: STAGES-1 stages in flight
    #pragma unroll
    for (int s = 0; s < STAGES - 1; s++){
        if (s < KT) issue(s, s);
        cp_commit();
    }

    for (int kt = 0; kt < KT; kt++){
        cp_wait<STAGES - 2>();
        __syncthreads();
        const int nx = kt + STAGES - 1;
        if (nx < KT) issue(nx, nx % STAGES);
        cp_commit();                               // always commit: keeps group count aligned
        compute(kt % STAGES);
    }

    // epilogue
    #pragma unroll
    for (int mf = 0; mf < 4; mf++){
        #pragma unroll
        for (int nf = 0; nf < NF; nf++){
            const int r0 = m0 + wm + mf * 16 + gid;
            const int r1 = r0 + 8;
            const int c  = n0 + wn + nf * 8 + 2 * tg;
            const float* a0v = acc0[mf][nf];
            if (DUAL){
                const float* a1v = acc1[DUAL ? mf : 0][nf];
                float* Cb = (MODE == MODE_GU_SH) ? g_sg : g_h1;   // device-side
                float2 v0 = make_float2(to_tf32f(siluf(a0v[0]) * a1v[0]),
                                        to_tf32f(siluf(a0v[1]) * a1v[1]));
                float2 v1 = make_float2(to_tf32f(siluf(a0v[2]) * a1v[2]),
                                        to_tf32f(siluf(a0v[3]) * a1v[3]));
                *(float2*)&Cb[(size_t)r0 * N + c] = v0;
                *(float2*)&Cb[(size_t)r1 * N + c] = v1;
            } else if (MODE == MODE_DN_SH){
                const float s0 = g_gate[r0], s1 = g_gate[r1];
                float2 v0 = make_float2(a0v[0] * s0, a0v[1] * s0);
                float2 v1 = make_float2(a0v[2] * s1, a0v[3] * s1);
                *(float2*)&Cout[(size_t)r0 * N + c] = v0;
                *(float2*)&Cout[(size_t)r1 * N + c] = v1;
            } else { // MODE_DN_EX
                const float s0 = g_roww[r0], s1 = g_roww[r1];
                float2 v0 = make_float2(a0v[0] * s0, a0v[1] * s0);
                float2 v1 = make_float2(a0v[2] * s1, a0v[3] * s1);
                *(float2*)&g_dout[(size_t)r0 * N + c] = v0;
                *(float2*)&g_dout[(size_t)r1 * N + c] = v1;
            }
        }
    }
}

// ---------------- launch ----------------
extern "C" void kernel_launch(void* const* d_in, const int* in_sizes, int n_in,
                              void* d_out, int out_size)
{
    (void)in_sizes; (void)n_in; (void)out_size;

    const float* x      = (const float*)d_in[0];
    const float* Wr     = (const float*)d_in[1];
    const float* Wg     = (const float*)d_in[2];
    const float* Wu     = (const float*)d_in[3];
    const float* Wd     = (const float*)d_in[4];
    const float* Wsg    = (const float*)d_in[5];
    const float* Wsu    = (const float*)d_in[6];
    const float* Wsd    = (const float*)d_in[7];
    const float* Wsgate = (const float*)d_in[8];

    float* out    = (float*)d_out;
    float* logits = out + (size_t)TTOK * HDIM;

    const int SMEM_DUAL = 3 * 9216 * 4;   // 110592 B
    const int SMEM_SGL  = 3 * 8960 * 4;   // 107520 B
    cudaFuncSetAttribute(gemm_kernel<MODE_GU_SH>, cudaFuncAttributeMaxDynamicSharedMemorySize, SMEM_DUAL);
    cudaFuncSetAttribute(gemm_kernel<MODE_GU_EX>, cudaFuncAttributeMaxDynamicSharedMemorySize, SMEM_DUAL);
    cudaFuncSetAttribute(gemm_kernel<MODE_DN_SH>, cudaFuncAttributeMaxDynamicSharedMemorySize, SMEM_SGL);
    cudaFuncSetAttribute(gemm_kernel<MODE_DN_EX>, cudaFuncAttributeMaxDynamicSharedMemorySize, SMEM_SGL);

    // launch order chosen so the profiler's sample index lands on the big GEMM
    init_kernel<<<(ROWCAP + 255) / 256, 256>>>();                                   // 0
    preround_kernel<<<dim3(16384, 7), 256>>>((const float4*)x, (const float4*)Wg,   // 1
                                             (const float4*)Wu, (const float4*)Wd,
                                             (const float4*)Wsg, (const float4*)Wsu,
                                             (const float4*)Wsd);
    router_kernel<<<TTOK / 64, 64>>>(x, Wr, Wsgate, logits);                        // 2

    {   // 3: shared expert gate+up SwiGLU  (profiler target)
        int gm = TTOK / 128, gn = ISDIM / 64;
        gemm_kernel<MODE_GU_SH><<<gm * gn, 128, SMEM_DUAL>>>(nullptr, HDIM, ISDIM, gm, gn);
    }

    scan_kernel<<<1, 32>>>();                                                       // 4
    scatter_kernel<<<TTOK / 256, 256>>>();                                          // 5

    {   // shared expert down (sigmoid-gated) -> out
        int gm = TTOK / 128, gn = HDIM / 128;
        gemm_kernel<MODE_DN_SH><<<gm * gn, 128, SMEM_SGL>>>(out, ISDIM, HDIM, gm, gn);
    }
    {   // expert gate+up SwiGLU (gathered rows)
        int gm = ROWCAP / 128, gn = IDIM / 64;
        gemm_kernel<MODE_GU_EX><<<gm * gn, 128, SMEM_DUAL>>>(nullptr, HDIM, IDIM, gm, gn);
    }
    {   // expert down (routing weight folded) -> g_dout
        int gm = ROWCAP / 128, gn = HDIM / 128;
        gemm_kernel<MODE_DN_EX><<<gm * gn, 128, SMEM_SGL>>>(nullptr, IDIM, HDIM, gm, gn);
    }

    // out += dout[slot0] + dout[slot1]
    combine_kernel<<<(TTOK * HDIM / 4) / 256, 256>>>(out);
}

// round 17
// speedup vs baseline: 1.2179x; 1.2163x over previous
#include <cuda_runtime.h>
#include <cstdint>
#include <cstddef>

#define HDIM   2048
#define NEXP   8
#define IDIM   1024
#define ISDIM  4096
#define TTOK   4096
#define ROWCAP 9216   // 2*TTOK + NEXP*128 padding

// ---------------- scratch (__device__ globals; no allocation allowed) ----------------
// k-blocked, swizzled layouts: [K/32][rows][32], 128B rows, chunk ^= row&7
__device__ float g_xb  [(size_t)TTOK * HDIM];          // x blocked          (A for GU_SH)
__device__ float g_xg  [(size_t)ROWCAP * HDIM];        // gathered x blocked (A for GU_EX)
__device__ float g_sgb [(size_t)TTOK * ISDIM];         // shared SwiGLU out  (A for DN_SH)
__device__ float g_h1b [(size_t)ROWCAP * IDIM];        // expert SwiGLU out  (A for DN_EX)
__device__ float g_wsgb[(size_t)HDIM * ISDIM];         // B blocked weights
__device__ float g_wsub[(size_t)HDIM * ISDIM];
__device__ float g_wsdb[(size_t)ISDIM * HDIM];
__device__ float g_wgb [(size_t)NEXP * HDIM * IDIM];
__device__ float g_wub [(size_t)NEXP * HDIM * IDIM];
__device__ float g_wdb [(size_t)NEXP * IDIM * HDIM];

__device__ float g_dout[(size_t)ROWCAP * HDIM];        // expert down output (row-major)
__device__ int   g_rowmap[ROWCAP];
__device__ float g_roww[ROWCAP];
__device__ int   g_slot[TTOK * 2];
__device__ int   g_tokidx[TTOK * 2];
__device__ float g_tokw[TTOK * 2];
__device__ float g_gate[TTOK];
__device__ int   g_cnt[NEXP];
__device__ int   g_cursor[NEXP];
__device__ int   g_poff[NEXP + 1];

// ---------------- helpers ----------------
__device__ __forceinline__ float to_tf32f(float x){
    unsigned u; asm("cvt.rna.tf32.f32 %0, %1;" : "=r"(u) : "f"(x));
    return __uint_as_float(u);
}
__device__ __forceinline__ float siluf(float x){
    return x * (1.f / (1.f + __expf(-x)));
}
__device__ __forceinline__ void mma_tf32(float* d, const unsigned* a, const unsigned* b){
    asm volatile("mma.sync.aligned.m16n8k8.row.col.f32.tf32.tf32.f32 "
                 "{%0,%1,%2,%3}, {%4,%5,%6,%7}, {%8,%9}, {%0,%1,%2,%3};\n"
                 : "+f"(d[0]), "+f"(d[1]), "+f"(d[2]), "+f"(d[3])
                 : "r"(a[0]), "r"(a[1]), "r"(a[2]), "r"(a[3]),
                   "r"(b[0]), "r"(b[1]));
}
__device__ __forceinline__ void bulk_g2s(unsigned dst, const void* src, unsigned bytes,
                                         unsigned mbar){
    asm volatile("cp.async.bulk.shared::cluster.global.mbarrier::complete_tx::bytes "
                 "[%0], [%1], %2, [%3];\n"
                 :: "r"(dst), "l"(src), "r"(bytes), "r"(mbar) : "memory");
}
__device__ __forceinline__ void mbar_init(uint32_t addr, uint32_t cnt){
    asm volatile("mbarrier.init.shared.b64 [%0], %1;" :: "r"(addr), "r"(cnt) : "memory");
}
__device__ __forceinline__ void mbar_expect_tx(uint32_t addr, uint32_t bytes){
    asm volatile("mbarrier.arrive.expect_tx.shared.b64 _, [%0], %1;"
                 :: "r"(addr), "r"(bytes) : "memory");
}
__device__ __forceinline__ void mbar_wait(uint32_t addr, int parity){
    asm volatile("{\n\t.reg .pred P1;\n\t"
                 "WAIT_LOOP_%=:\n\t"
                 "mbarrier.try_wait.parity.acquire.cta.shared::cta.b64 P1, [%0], %1, 0x989680;\n\t"
                 "@P1 bra.uni WAIT_DONE_%=;\n\t"
                 "bra.uni WAIT_LOOP_%=;\n\t"
                 "WAIT_DONE_%=:\n\t}"
                 :: "r"(addr), "r"((unsigned)parity) : "memory");
}
__device__ __forceinline__ void fence_proxy_async_cta(){
    asm volatile("fence.proxy.async.shared::cta;" ::: "memory");
}

// ---------------- small kernels ----------------
__global__ void init_kernel(){
    int i = blockIdx.x * 256 + threadIdx.x;
    if (i < ROWCAP){ g_rowmap[i] = -1; g_roww[i] = 0.f; }
    if (i < NEXP){ g_cnt[i] = 0; g_cursor[i] = 0; }
}

// prep: write weights + x into k-blocked swizzled layouts (tf32-rounded).
// blockIdx ranges: [0,8192) Wsg  [8192,16384) Wsu  [16384,24576) Wsd
//                  [24576,40960) Wg  [40960,57344) Wu  [57344,73728) Wd
//                  [73728,81920) x -> g_xb
__global__ void prep_kernel(const float* __restrict__ x,
                            const float* __restrict__ wsg, const float* __restrict__ wsu,
                            const float* __restrict__ wsd, const float* __restrict__ wg,
                            const float* __restrict__ wu,  const float* __restrict__ wd)
{
    __shared__ float t32[32][33];
    int b = blockIdx.x;
    const int tid = threadIdx.x;

    if (b >= 73728){    // x -> g_xb: (kt, 32-token group); per-row copy with swizzle
        const int q  = b - 73728;
        const int kt = q >> 7;
        const int t  = (q & 127) * 32 + (tid >> 3);
        const int p  = tid & 7;
        float4 v = ((const float4*)x)[(size_t)t * 512 + kt * 8 + (p ^ (t & 7))];
        v.x = to_tf32f(v.x); v.y = to_tf32f(v.y);
        v.z = to_tf32f(v.z); v.w = to_tf32f(v.w);
        ((float4*)g_xb)[((size_t)kt * TTOK + t) * 8 + p] = v;
        return;
    }

    // B-type: 32x32 transpose tile into blocked layout [K/32][N][32] (swizzled)
    const float* src; float* dst; int N;
    if (b < 8192)      {             src = wsg; dst = g_wsgb; N = ISDIM; }
    else if (b < 16384){ b -= 8192;  src = wsu; dst = g_wsub; N = ISDIM; }
    else if (b < 24576){ b -= 16384; src = wsd; dst = g_wsdb; N = HDIM;  }
    else if (b < 40960){ b -= 24576; int e = b >> 11; b &= 2047;
                         src = wg + (size_t)e * HDIM * IDIM; dst = g_wgb + (size_t)e * HDIM * IDIM;
                         N = IDIM; }
    else if (b < 57344){ b -= 40960; int e = b >> 11; b &= 2047;
                         src = wu + (size_t)e * HDIM * IDIM; dst = g_wub + (size_t)e * HDIM * IDIM;
                         N = IDIM; }
    else               { b -= 57344; int e = b >> 11; b &= 2047;
                         src = wd + (size_t)e * IDIM * HDIM; dst = g_wdb + (size_t)e * IDIM * HDIM;
                         N = HDIM; }

    const int ntiles = N >> 5;
    const int kt = b / ntiles;
    const int n0 = (b - kt * ntiles) * 32;
    const int tx = tid & 31, ty = tid >> 5;   // 32 x 8

    #pragma unroll
    for (int q = 0; q < 4; q++){
        const int k = ty + q * 8;
        t32[k][tx] = src[(size_t)(kt * 32 + k) * N + n0 + tx];
    }
    __syncthreads();

    // dst row = n0+tx; dst chunk ty holds src chunk (ty ^ (n&7))
    const int c = (ty ^ (tx & 7)) * 4;
    float4 v;
    v.x = to_tf32f(t32[c    ][tx]);
    v.y = to_tf32f(t32[c + 1][tx]);
    v.z = to_tf32f(t32[c + 2][tx]);
    v.w = to_tf32f(t32[c + 3][tx]);
    ((float4*)dst)[((size_t)kt * N + n0 + tx) * 8 + ty] = v;
}

// gather tokens into g_xg blocked layout (rows = gathered slots; pads -> 0)
__global__ void gather_kernel(const float* __restrict__ x){
    const int q  = blockIdx.x;
    const int kt = q / (ROWCAP / 32);
    const int r  = (q % (ROWCAP / 32)) * 32 + (threadIdx.x >> 3);
    const int p  = threadIdx.x & 7;
    const int tk = g_rowmap[r];
    float4 v = make_float4(0.f, 0.f, 0.f, 0.f);
    if (tk >= 0){
        v = ((const float4*)x)[(size_t)tk * 512 + kt * 8 + (p ^ (r & 7))];
        v.x = to_tf32f(v.x); v.y = to_tf32f(v.y);
        v.z = to_tf32f(v.z); v.w = to_tf32f(v.w);
    }
    ((float4*)g_xg)[((size_t)kt * ROWCAP + r) * 8 + p] = v;
}

__global__ void router_kernel(const float* __restrict__ x,
                              const float* __restrict__ Wr,
                              const float* __restrict__ Wsgate,
                              float* __restrict__ logits_out)
{
    __shared__ float sW[128 * 8];
    __shared__ float sG[128];
    const int tok = blockIdx.x * 64 + threadIdx.x;

    float acc[9];
    #pragma unroll
    for (int e = 0; e < 9; e++) acc[e] = 0.f;

    for (int h0 = 0; h0 < HDIM; h0 += 128){
        __syncthreads();
        for (int i = threadIdx.x; i < 1024; i += 64) sW[i] = Wr[h0 * NEXP + i];
        for (int i = threadIdx.x; i < 128;  i += 64) sG[i] = Wsgate[h0 + i];
        __syncthreads();

        const float4* xr = (const float4*)(x + (size_t)tok * HDIM + h0);
        for (int k4 = 0; k4 < 32; k4++){
            float4 xv = xr[k4];
            float xs[4] = {xv.x, xv.y, xv.z, xv.w};
            #pragma unroll
            for (int j = 0; j < 4; j++){
                const int kk = k4 * 4 + j;
                const float xj = xs[j];
                #pragma unroll
                for (int e = 0; e < 8; e++)
                    acc[e] = fmaf(xj, sW[kk * 8 + e], acc[e]);
                acc[8] = fmaf(xj, sG[kk], acc[8]);
            }
        }
    }

    float4* lo = (float4*)(logits_out + (size_t)tok * 8);
    lo[0] = make_float4(acc[0], acc[1], acc[2], acc[3]);
    lo[1] = make_float4(acc[4], acc[5], acc[6], acc[7]);

    float mx = acc[0];
    #pragma unroll
    for (int e = 1; e < 8; e++) mx = fmaxf(mx, acc[e]);
    float ex[8];
    #pragma unroll
    for (int e = 0; e < 8; e++) ex[e] = __expf(acc[e] - mx);

    int i0 = 0; float v0 = ex[0];
    #pragma unroll
    for (int e = 1; e < 8; e++) if (ex[e] > v0){ v0 = ex[e]; i0 = e; }
    int i1 = -1; float v1 = -1.f;
    #pragma unroll
    for (int e = 0; e < 8; e++) if (e != i0 && ex[e] > v1){ v1 = ex[e]; i1 = e; }

    const float ws = v0 + v1;
    g_tokidx[2 * tok]     = i0;
    g_tokidx[2 * tok + 1] = i1;
    g_tokw[2 * tok]       = v0 / ws;
    g_tokw[2 * tok + 1]   = v1 / ws;
    g_gate[tok] = 1.f / (1.f + __expf(-acc[8]));

    atomicAdd(&g_cnt[i0], 1);
    atomicAdd(&g_cnt[i1], 1);
}

__global__ void scan_kernel(){
    if (threadIdx.x == 0 && blockIdx.x == 0){
        int off = 0;
        for (int e = 0; e < NEXP; e++){
            g_poff[e] = off;
            off += (g_cnt[e] + 127) & ~127;
        }
        g_poff[NEXP] = off;
    }
}

__global__ void scatter_kernel(){
    const int t = blockIdx.x * 256 + threadIdx.x;
    if (t >= TTOK) return;
    #pragma unroll
    for (int k = 0; k < 2; k++){
        const int e   = g_tokidx[2 * t + k];
        const int pos = g_poff[e] + atomicAdd(&g_cursor[e], 1);
        g_rowmap[pos] = t;
        g_roww[pos]   = g_tokw[2 * t + k];
        g_slot[2 * t + k] = pos;
    }
}

__global__ void combine_kernel(float* __restrict__ out){
    const int i = blockIdx.x * 256 + threadIdx.x;
    const int t = i >> 9;
    const int c = i & 511;
    const int s0 = g_slot[2 * t];
    const int s1 = g_slot[2 * t + 1];
    float4 o = ((float4*)out)[i];
    float4 a = ((const float4*)g_dout)[(size_t)s0 * 512 + c];
    float4 b = ((const float4*)g_dout)[(size_t)s1 * 512 + c];
    o.x += a.x + b.x; o.y += a.y + b.y; o.z += a.z + b.z; o.w += a.w + b.w;
    ((float4*)out)[i] = o;
}

// ---------------- bulk-copy pipelined TF32 GEMM ----------------
// BM=128; DUAL: BN=64 (two Bs), SINGLE: BN=128. K-tile=32. 128 threads, 4 warps.
// Operands in k-blocked swizzled gmem -> each stage tile is ONE contiguous
// 8/16KB region, fetched by cp.async.bulk (UBLKCP) + mbarrier. 3x32KB stages,
// 2 CTAs/SM. Fragment LDS conflict-free via the baked XOR swizzle.
enum { MODE_GU_SH = 0, MODE_GU_EX = 1, MODE_DN_SH = 2, MODE_DN_EX = 3 };

template<int MODE>
__global__ __launch_bounds__(128, 2)
void gemm_kernel(float* __restrict__ Cout, int K, int N, int grid_m, int grid_n)
{
    constexpr bool DUAL   = (MODE == MODE_GU_SH || MODE == MODE_GU_EX);
    constexpr bool EXPERT = (MODE == MODE_GU_EX || MODE == MODE_DN_EX);
    constexpr int  BN     = DUAL ? 64 : 128;
    constexpr int  NF     = DUAL ? 4 : 8;
    constexpr unsigned ABYTES = 16384;
    constexpr unsigned BBYTES = DUAL ? 8192u : 16384u;
    constexpr unsigned STAGEB = 32768;

    extern __shared__ float smem[];
    const uint32_t sm_base = (uint32_t)__cvta_generic_to_shared(smem);
    const int tid = threadIdx.x;

    // device-side operand selection (k-blocked arrays; rows of the A array)
    const float* A;  size_t Arows;
    const float* B0; const float* B1 = nullptr;
    if (MODE == MODE_GU_SH){ A = g_xb;  Arows = TTOK;   B0 = g_wsgb; B1 = g_wsub; }
    if (MODE == MODE_GU_EX){ A = g_xg;  Arows = ROWCAP; B0 = g_wgb;  B1 = g_wub;  }
    if (MODE == MODE_DN_SH){ A = g_sgb; Arows = TTOK;   B0 = g_wsdb; }
    if (MODE == MODE_DN_EX){ A = g_h1b; Arows = ROWCAP; B0 = g_wdb;  }

    // rasterized block mapping
    const int GROUPM = 8;
    int lin = blockIdx.x;
    int per = GROUPM * grid_n;
    int g   = lin / per;
    int rem = lin - g * per;
    int gm  = min(GROUPM, grid_m - g * GROUPM);
    const int m0 = (g * GROUPM + rem % gm) * 128;
    const int n0 = (rem / gm) * BN;

    if (EXPERT){
        if (m0 >= g_poff[NEXP]) return;
        int e = 0;
        while (m0 >= g_poff[e + 1]) e++;
        const size_t boff = (size_t)e * K * N;
        B0 += boff;
        if (DUAL) B1 += boff;
    }

    // mbarriers (full[3]) at smem base; stages at +1024 bytes
    if (tid == 0){
        mbar_init(sm_base,      1);
        mbar_init(sm_base + 8,  1);
        mbar_init(sm_base + 16, 1);
        fence_proxy_async_cta();
    }
    __syncthreads();

    const int KT = K >> 5;

    auto issue = [&](int kt, int st){
        const unsigned sb = sm_base + 1024 + st * STAGEB;
        mbar_expect_tx(sm_base + 8 * st, STAGEB);
        bulk_g2s(sb,          A  + ((size_t)kt * Arows + m0) * 32, ABYTES, sm_base + 8 * st);
        bulk_g2s(sb + ABYTES, B0 + ((size_t)kt * N + n0) * 32, BBYTES, sm_base + 8 * st);
        if (DUAL)
            bulk_g2s(sb + ABYTES + BBYTES, B1 + ((size_t)kt * N + n0) * 32, BBYTES,
                     sm_base + 8 * st);
    };

    if (tid == 0){
        issue(0, 0);
        if (KT > 1) issue(1, 1);
        if (KT > 2) issue(2, 2);
    }

    // warp / lane coords (2x2 warp grid)
    const int wid  = tid >> 5;
    const int wm   = (wid & 1) * 64;
    const int wn   = (wid >> 1) * (DUAL ? 32 : 64);
    const int lane = tid & 31;
    const int gid  = lane >> 2;
    const int tg   = lane & 3;

    float acc0[4][NF][4];
    float acc1[DUAL ? 4 : 1][NF][4];
    #pragma unroll
    for (int a = 0; a < 4; a++)
        #pragma unroll
        for (int b = 0; b < NF; b++)
            #pragma unroll
            for (int c = 0; c < 4; c++){
                acc0[a][b][c] = 0.f;
                if (DUAL) acc1[DUAL ? a : 0][b][c] = 0.f;
            }

    int ph[3] = {0, 0, 0};

    for (int kt = 0; kt < KT; kt++){
        const int st = kt % 3;
        mbar_wait(sm_base + 8 * st, ph[st]);
        ph[st] ^= 1;

        const float* Asb = smem + 256 + st * 8192;
        const float* B0b = Asb + 4096;
        const float* B1b = B0b + (DUAL ? 2048 : 0);

        #pragma unroll
        for (int ks = 0; ks < 4; ks++){
            const int kq = ks * 2;              // (ks*8)/4
            unsigned af[4][4];
            #pragma unroll
            for (int mf = 0; mf < 4; mf++){
                const int mr = wm + mf * 16 + gid;
                const int s0 = ((kq    ) ^ (mr & 7)) << 2;
                const int s1 = ((kq + 1) ^ (mr & 7)) << 2;
                af[mf][0] = __float_as_uint(Asb[ mr      * 32 + s0 + tg]);
                af[mf][1] = __float_as_uint(Asb[(mr + 8) * 32 + s0 + tg]);
                af[mf][2] = __float_as_uint(Asb[ mr      * 32 + s1 + tg]);
                af[mf][3] = __float_as_uint(Asb[(mr + 8) * 32 + s1 + tg]);
            }
            unsigned bf0[NF][2], bf1[NF][2];
            #pragma unroll
            for (int nf = 0; nf < NF; nf++){
                const int nc = wn + nf * 8 + gid;
                const int s0 = ((kq    ) ^ (nc & 7)) << 2;
                const int s1 = ((kq + 1) ^ (nc & 7)) << 2;
                bf0[nf][0] = __float_as_uint(B0b[nc * 32 + s0 + tg]);
                bf0[nf][1] = __float_as_uint(B0b[nc * 32 + s1 + tg]);
                if (DUAL){
                    bf1[nf][0] = __float_as_uint(B1b[nc * 32 + s0 + tg]);
                    bf1[nf][1] = __float_as_uint(B1b[nc * 32 + s1 + tg]);
                }
            }
            #pragma unroll
            for (int mf = 0; mf < 4; mf++)
                #pragma unroll
                for (int nf = 0; nf < NF; nf++){
                    mma_tf32(acc0[mf][nf], af[mf], bf0[nf]);
                    if (DUAL) mma_tf32(acc1[DUAL ? mf : 0][nf], af[mf], bf1[nf]);
                }
        }

        __syncthreads();                         // everyone done reading stage st
        if (tid == 0 && kt + 3 < KT) issue(kt + 3, st);
    }

    // epilogue
    #pragma unroll
    for (int mf = 0; mf < 4; mf++){
        #pragma unroll
        for (int nf = 0; nf < NF; nf++){
            const int r0 = m0 + wm + mf * 16 + gid;
            const int r1 = r0 + 8;
            const int c  = n0 + wn + nf * 8 + 2 * tg;
            const float* a0v = acc0[mf][nf];
            if (DUAL){
                const float* a1v = acc1[DUAL ? mf : 0][nf];
                float* Cb = (MODE == MODE_GU_SH) ? g_sgb : g_h1b;
                const size_t Tr = (MODE == MODE_GU_SH) ? TTOK : ROWCAP;
                const int cc = c & 31;
                const int sw = ((((cc >> 2) ^ (r0 & 7)) << 2) | (cc & 3));
                const size_t base = ((size_t)(c >> 5) * Tr) * 32 + sw;
                float2 v0 = make_float2(to_tf32f(siluf(a0v[0]) * a1v[0]),
                                        to_tf32f(siluf(a0v[1]) * a1v[1]));
                float2 v1 = make_float2(to_tf32f(siluf(a0v[2]) * a1v[2]),
                                        to_tf32f(siluf(a0v[3]) * a1v[3]));
                *(float2*)&Cb[base + (size_t)r0 * 32] = v0;
                *(float2*)&Cb[base + (size_t)r1 * 32] = v1;
            } else if (MODE == MODE_DN_SH){
                const float s0 = g_gate[r0], s1 = g_gate[r1];
                float2 v0 = make_float2(a0v[0] * s0, a0v[1] * s0);
                float2 v1 = make_float2(a0v[2] * s1, a0v[3] * s1);
                *(float2*)&Cout[(size_t)r0 * N + c] = v0;
                *(float2*)&Cout[(size_t)r1 * N + c] = v1;
            } else { // MODE_DN_EX
                const float s0 = g_roww[r0], s1 = g_roww[r1];
                float2 v0 = make_float2(a0v[0] * s0, a0v[1] * s0);
                float2 v1 = make_float2(a0v[2] * s1, a0v[3] * s1);
                *(float2*)&g_dout[(size_t)r0 * N + c] = v0;
                *(float2*)&g_dout[(size_t)r1 * N + c] = v1;
            }
        }
    }
}

// ---------------- launch ----------------
extern "C" void kernel_launch(void* const* d_in, const int* in_sizes, int n_in,
                              void* d_out, int out_size)
{
    (void)in_sizes; (void)n_in; (void)out_size;

    const float* x      = (const float*)d_in[0];
    const float* Wr     = (const float*)d_in[1];
    const float* Wg     = (const float*)d_in[2];
    const float* Wu     = (const float*)d_in[3];
    const float* Wd     = (const float*)d_in[4];
    const float* Wsg    = (const float*)d_in[5];
    const float* Wsu    = (const float*)d_in[6];
    const float* Wsd    = (const float*)d_in[7];
    const float* Wsgate = (const float*)d_in[8];

    float* out    = (float*)d_out;
    float* logits = out + (size_t)TTOK * HDIM;

    const int SMEM = 1024 + 3 * 32768;   // 99328 B (all modes)
    cudaFuncSetAttribute(gemm_kernel<MODE_GU_SH>, cudaFuncAttributeMaxDynamicSharedMemorySize, SMEM);
    cudaFuncSetAttribute(gemm_kernel<MODE_GU_EX>, cudaFuncAttributeMaxDynamicSharedMemorySize, SMEM);
    cudaFuncSetAttribute(gemm_kernel<MODE_DN_SH>, cudaFuncAttributeMaxDynamicSharedMemorySize, SMEM);
    cudaFuncSetAttribute(gemm_kernel<MODE_DN_EX>, cudaFuncAttributeMaxDynamicSharedMemorySize, SMEM);

    init_kernel<<<(ROWCAP + 255) / 256, 256>>>();                                   // 0
    prep_kernel<<<81920, 256>>>(x, Wsg, Wsu, Wsd, Wg, Wu, Wd);                      // 1
    router_kernel<<<TTOK / 64, 64>>>(x, Wr, Wsgate, logits);                        // 2

    {   // 3: shared expert gate+up SwiGLU  (profiler target)
        int gm = TTOK / 128, gn = ISDIM / 64;
        gemm_kernel<MODE_GU_SH><<<gm * gn, 128, SMEM>>>(nullptr, HDIM, ISDIM, gm, gn);
    }

    scan_kernel<<<1, 32>>>();                                                       // 4
    scatter_kernel<<<TTOK / 256, 256>>>();                                          // 5
    gather_kernel<<<64 * (ROWCAP / 32), 256>>>(x);                                  // 6

    {   // shared expert down (sigmoid-gated) -> out
        int gm = TTOK / 128, gn = HDIM / 128;
        gemm_kernel<MODE_DN_SH><<<gm * gn, 128, SMEM>>>(out, ISDIM, HDIM, gm, gn);
    }
    {   // expert gate+up SwiGLU (dense on gathered rows)
        int gm = ROWCAP / 128, gn = IDIM / 64;
        gemm_kernel<MODE_GU_EX><<<gm * gn, 128, SMEM>>>(nullptr, HDIM, IDIM, gm, gn);
    }
    {   // expert down (routing weight folded) -> g_dout
        int gm = ROWCAP / 128, gn = HDIM / 128;
        gemm_kernel<MODE_DN_EX><<<gm * gn, 128, SMEM>>>(nullptr, IDIM, HDIM, gm, gn);
    }

    // out += dout[slot0] + dout[slot1]
    combine_kernel<<<(TTOK * HDIM / 4) / 256, 256>>>(out);
}